// round 16
// baseline (speedup 1.0000x reference)
#include <cuda_runtime.h>
#include <cuda_bf16.h>
#include <math.h>
#include <stdint.h>

#define Bb 4
#define Ss 4096
#define Hh 2048
#define Mm 128
#define CH 64
#define NC 64
#define NSLOTS 64
#define NTOK (Bb*Ss)   // 16384

// ---------------- scratch ----------------
__device__ float g_q[NTOK*Mm];
__device__ float g_k[NTOK*Mm];
__device__ float g_v[NTOK*Mm];
__device__ float g_w[NTOK];
__device__ float g_ss[NTOK*16];
__device__ float g_Kagg[NSLOTS*Mm];
__device__ float g_Vagg[NSLOTS*Mm];
__device__ float g_ws[NSLOTS];
__device__ __align__(128) unsigned char g_rs [(size_t)NTOK * Mm * 4];
__device__ __align__(128) unsigned char g_wqs[(size_t)Mm * Hh * 4];
__device__ __align__(128) unsigned char g_wks[(size_t)Mm * Hh * 4];
__device__ __align__(128) unsigned char g_wvs[(size_t)Mm * Hh * 4];
__device__ __align__(128) unsigned char g_wos[(size_t)Hh * Mm * 4];

// ================= helpers =================
__device__ __forceinline__ uint32_t smem_u32(const void* p){
    uint32_t a;
    asm("{ .reg .u64 t; cvta.to.shared.u64 t, %1; cvt.u32.u64 %0, t; }" : "=r"(a) : "l"(p));
    return a;
}
__device__ __forceinline__ uint32_t bf2(float x, float y){
    uint32_t r; asm("cvt.rn.bf16x2.f32 %0, %1, %2;" : "=r"(r) : "f"(y), "f"(x)); return r;
}
__device__ __forceinline__ uint32_t swz(uint32_t x){ return x ^ (((x) >> 3) & 0x70); }

__device__ __forceinline__ void pack4(float4 a, uint2& h, uint2& lo){
    h.x = bf2(a.x, a.y); h.y = bf2(a.z, a.w);
    float l0 = a.x - __uint_as_float(h.x << 16);
    float l1 = a.y - __uint_as_float(h.x & 0xffff0000u);
    float l2 = a.z - __uint_as_float(h.y << 16);
    float l3 = a.w - __uint_as_float(h.y & 0xffff0000u);
    lo.x = bf2(l0, l1); lo.y = bf2(l2, l3);
}
__device__ __forceinline__ void pack8(float4 a0, float4 a1, uint4& h, uint4& lo){
    uint2 h0, l0, h1, l1;
    pack4(a0, h0, l0); pack4(a1, h1, l1);
    h.x = h0.x; h.y = h0.y; h.z = h1.x; h.w = h1.y;
    lo.x = l0.x; lo.y = l0.y; lo.z = l1.x; lo.w = l1.y;
}

#define LDSM4(r, addr) \
    asm volatile("ldmatrix.sync.aligned.m8n8.x4.shared.b16 {%0,%1,%2,%3}, [%4];" \
        : "=r"((r)[0]), "=r"((r)[1]), "=r"((r)[2]), "=r"((r)[3]) : "r"(addr))

#define MMA16816(d, a, b0, b1) \
    asm volatile("mma.sync.aligned.m16n8k16.row.col.f32.bf16.bf16.f32 " \
        "{%0,%1,%2,%3}, {%4,%5,%6,%7}, {%8,%9}, {%0,%1,%2,%3};" \
        : "+f"((d)[0]), "+f"((d)[1]), "+f"((d)[2]), "+f"((d)[3]) \
        : "r"((a)[0]), "r"((a)[1]), "r"((a)[2]), "r"((a)[3]), "r"(b0), "r"(b1))

#define CP16(dst, src) \
    asm volatile("cp.async.cg.shared.global [%0], [%1], 16;" :: "r"(dst), "l"(src) : "memory")
#define CP_COMMIT() asm volatile("cp.async.commit_group;" ::: "memory")
#define CP_WAIT1()  asm volatile("cp.async.wait_group 1;" ::: "memory")

// ======================================================================
// mega_proj v6: out_mma-shaped. One z per CTA, 128x128 tile, 256 thr,
// 8 warps, in-CTA A split, 3-stage B ring, double ABF, 88KB smem
// -> 2 CTAs/SM. Grid dim3(3,128), z fastest (x-tile L2 sharing).
// ======================================================================
#define P6_BSP(s)   ((s) * 16384)            // B stages: 0..49151
#define P6_ABF(p)   (49152 + (p) * 16384)    // A bf16 double buffer
#define P6_WG       81920
#define MEGA6_SMEM  90112                    // 88 KB

__global__ void __launch_bounds__(256, 2) mega_proj6(const float* __restrict__ x,
                                                     const float* __restrict__ Wg,
                                                     const float* __restrict__ gb)
{
    extern __shared__ __align__(1024) char smem[];
    __shared__ float gred[128][2];
    int tid = threadIdx.x;
    int w = tid >> 5, l = tid & 31;
    int z = blockIdx.x;           // 0=q 1=k 2=v
    int m0 = blockIdx.y * 128;
    uint32_t smb = smem_u32(smem);
    const int NB = Hh / 32;       // 64

    const unsigned char* Bsrc = (z == 0) ? g_wqs : (z == 1) ? g_wks : g_wvs;
    float* C = (z == 0) ? g_q : (z == 1) ? g_k : g_v;
    unsigned long long gB = (unsigned long long)__cvta_generic_to_global(Bsrc);

    bool dogate = (z == 0);
    if (dogate) {
        const float4* wg4 = (const float4*)Wg;
        *(float4*)(smem + P6_WG + tid * 32)      = wg4[2 * tid];
        *(float4*)(smem + P6_WG + tid * 32 + 16) = wg4[2 * tid + 1];
    }

    int row  = tid >> 1;          // 0..127 (A row owned by this thread)
    int half = tid & 1;           // which 16-col half of the 32-K block

    auto issueB = [&](int kb) {
        uint32_t stB = smb + P6_BSP(kb % 3);
#pragma unroll
        for (int u = 0; u < 4; u++) {
            int c = tid + (u << 8);               // 0..1023
            int r = c >> 3;
            uint32_t seg = (uint32_t)(c & 7) << 4;
            unsigned long long src = gB + ((unsigned long long)r * NB + kb) * 128ull + seg;
            CP16(stB + swz(((uint32_t)r << 7) + seg), src);
        }
    };

    auto ldgA = [&](int kb, float4* a) {
        const float* base = x + (size_t)(m0 + row) * Hh + (size_t)kb * 32 + half * 16;
#pragma unroll
        for (int j = 0; j < 4; j++) a[j] = __ldg((const float4*)(base + 4 * j));
    };

    float gp = 0.f;

    auto split_phase = [&](int kb, const float4* a) {
        char* abf = smem + P6_ABF(kb & 1);
        if (dogate) {
            const float* wgs = (const float*)(smem + P6_WG) + kb * 32 + half * 16;
#pragma unroll
            for (int j = 0; j < 4; j++)
                gp += a[j].x * wgs[4 * j] + a[j].y * wgs[4 * j + 1]
                    + a[j].z * wgs[4 * j + 2] + a[j].w * wgs[4 * j + 3];
        }
#pragma unroll
        for (int j = 0; j < 4; j++) {
            uint2 h, lo;
            pack4(a[j], h, lo);
            uint32_t b0 = (uint32_t)row * 128 + (uint32_t)(half * 4 + j) * 8;
            *(uint2*)(abf + swz(b0))      = h;
            *(uint2*)(abf + swz(b0 + 64)) = lo;
        }
    };

    float acc[2][8][4];
#pragma unroll
    for (int mi = 0; mi < 2; mi++)
#pragma unroll
        for (int nj = 0; nj < 8; nj++)
#pragma unroll
            for (int cc = 0; cc < 4; cc++) acc[mi][nj][cc] = 0.f;

    int wm = (w >> 1) << 5;   // 0,32,64,96
    int wn = (w & 1) << 6;    // 0,64
    int lr = l & 15, lh = l >> 4;

    // preamble
    issueB(0); CP_COMMIT();
    issueB(1); CP_COMMIT();
    float4 areg[4];
    ldgA(0, areg);
    __syncthreads();              // Wg preload visible before split reads it
    split_phase(0, areg);         // ABF[0]
    ldgA(1, areg);

    for (int kb = 0; kb < NB; kb++) {
        CP_WAIT1();
        __syncthreads();          // B stage kb + ABF[kb&1] visible; old buffers free
        if (kb + 2 < NB) issueB(kb + 2);
        CP_COMMIT();
        if (kb + 1 < NB) {
            split_phase(kb + 1, areg);
            int kn = (kb + 2 < NB) ? (kb + 2) : (NB - 1);
            ldgA(kn, areg);
        }

        uint32_t sAu = smb + P6_ABF(kb & 1);
        uint32_t sBu = smb + P6_BSP(kb % 3);
#pragma unroll
        for (int ks = 0; ks < 2; ks++) {
            uint32_t kbyte = (uint32_t)(ks << 5) + (lh << 4);
            uint32_t Ah[2][4], Al[2][4], Bh[4][4], Bl[4][4];
#pragma unroll
            for (int t = 0; t < 2; t++) {
                uint32_t ro = (uint32_t)((wm + (t << 4) + lr) << 7) + kbyte;
                LDSM4(Ah[t], sAu + swz(ro));
                LDSM4(Al[t], sAu + swz(ro + 64));
            }
#pragma unroll
            for (int g = 0; g < 4; g++) {
                uint32_t ro = (uint32_t)((wn + (g << 4) + lr) << 7) + kbyte;
                LDSM4(Bh[g], sBu + swz(ro));
                LDSM4(Bl[g], sBu + swz(ro + 64));
            }
#pragma unroll
            for (int mi = 0; mi < 2; mi++)
#pragma unroll
                for (int nj = 0; nj < 8; nj++) {
                    int g = nj >> 1, p = nj & 1;
                    MMA16816(acc[mi][nj], Ah[mi], Bh[g][p], Bh[g][p + 2]);
                    MMA16816(acc[mi][nj], Ah[mi], Bl[g][p], Bl[g][p + 2]);
                    MMA16816(acc[mi][nj], Al[mi], Bh[g][p], Bh[g][p + 2]);
                }
        }
    }

    // ---- gate reduce (z==0 CTAs only) ----
    if (dogate) {
        gred[row][half] = gp;
        __syncthreads();
        if (tid < 128) {
            float s = gred[tid][0] + gred[tid][1];
            g_w[m0 + tid] = 1.f / (1.f + expf(-(s + gb[0])));
        }
    }

    // ---- epilogue ----
#pragma unroll
    for (int mi = 0; mi < 2; mi++) {
        int r0 = wm + (mi << 4) + (l >> 2);
#pragma unroll
        for (int nj = 0; nj < 8; nj++) {
            float* p = C + (size_t)(m0 + r0) * Mm + wn + (nj << 3) + ((l & 3) << 1);
            *(float2*)p = make_float2(acc[mi][nj][0], acc[mi][nj][1]);
            *(float2*)(p + (size_t)8 * Mm) = make_float2(acc[mi][nj][2], acc[mi][nj][3]);
        }
    }
}

// ======================================================================
// out gemm (+ per-row ss partials): unchanged from R15
// ======================================================================
#define NSTG 2
#define STAGE_B 32768
#define GEMM_SMEM (NSTG * STAGE_B)   // 64 KB

__global__ void __launch_bounds__(256, 2) out_mma(float* __restrict__ out)
{
    extern __shared__ __align__(1024) char smem[];
    int n0 = blockIdx.y * 128;
    int m0 = blockIdx.x * 128;
    const unsigned char* As = g_rs;
    const unsigned char* Bs = g_wos + (size_t)n0 * 4 * 128;
    float* C = out + n0;
    const int NB = Mm / 32, ldc = Hh;

    int tid = threadIdx.x;
    int w = tid >> 5, l = tid & 31;
    uint32_t smb = smem_u32(smem);
    unsigned long long gA = (unsigned long long)__cvta_generic_to_global(As);
    unsigned long long gB = (unsigned long long)__cvta_generic_to_global(Bs);

    auto issue = [&](int kb) {
        uint32_t st = smb + (uint32_t)(kb & (NSTG - 1)) * STAGE_B;
#pragma unroll
        for (int u = 0; u < 4; u++) {
            int c = tid + (u << 8);
            int row = c >> 3;
            uint32_t seg = (uint32_t)(c & 7) << 4;
            unsigned long long srcA = gA + ((unsigned long long)(m0 + row) * NB + kb) * 128ull + seg;
            unsigned long long srcB = gB + ((unsigned long long)row * NB + kb) * 128ull + seg;
            uint32_t d = swz(((uint32_t)row << 7) + seg);
            CP16(st + d, srcA);
            CP16(st + 16384 + d, srcB);
        }
    };

    float acc[2][8][4];
#pragma unroll
    for (int mi = 0; mi < 2; mi++)
#pragma unroll
        for (int nj = 0; nj < 8; nj++)
#pragma unroll
            for (int cc = 0; cc < 4; cc++) acc[mi][nj][cc] = 0.f;

    int wm = (w >> 1) << 5;
    int wn = (w & 1) << 6;
    int lr = l & 15, lh = l >> 4;

    issue(0); CP_COMMIT();
    issue(1); CP_COMMIT();

    for (int kb = 0; kb < NB; kb++) {
        CP_WAIT1();
        __syncthreads();
        uint32_t sAu = smb + (uint32_t)(kb & (NSTG - 1)) * STAGE_B;
        uint32_t sBu = sAu + 16384;
#pragma unroll
        for (int ks = 0; ks < 2; ks++) {
            uint32_t kbyte = (uint32_t)(ks << 5) + (lh << 4);
            uint32_t Ah[2][4], Al[2][4], Bh[4][4], Bl[4][4];
#pragma unroll
            for (int t = 0; t < 2; t++) {
                uint32_t ro = (uint32_t)((wm + (t << 4) + lr) << 7) + kbyte;
                LDSM4(Ah[t], sAu + swz(ro));
                LDSM4(Al[t], sAu + swz(ro + 64));
            }
#pragma unroll
            for (int g = 0; g < 4; g++) {
                uint32_t ro = (uint32_t)((wn + (g << 4) + lr) << 7) + kbyte;
                LDSM4(Bh[g], sBu + swz(ro));
                LDSM4(Bl[g], sBu + swz(ro + 64));
            }
#pragma unroll
            for (int mi = 0; mi < 2; mi++)
#pragma unroll
                for (int nj = 0; nj < 8; nj++) {
                    int g = nj >> 1, p = nj & 1;
                    MMA16816(acc[mi][nj], Ah[mi], Bh[g][p], Bh[g][p + 2]);
                    MMA16816(acc[mi][nj], Ah[mi], Bl[g][p], Bl[g][p + 2]);
                    MMA16816(acc[mi][nj], Al[mi], Bh[g][p], Bh[g][p + 2]);
                }
        }
        __syncthreads();
        if (kb + NSTG < NB) issue(kb + NSTG);
        CP_COMMIT();
    }

#pragma unroll
    for (int mi = 0; mi < 2; mi++) {
        int r0 = wm + (mi << 4) + (l >> 2);
        float ss0 = 0.f, ss8 = 0.f;
#pragma unroll
        for (int nj = 0; nj < 8; nj++) {
            float* p = C + (size_t)(m0 + r0) * ldc + wn + (nj << 3) + ((l & 3) << 1);
            *(float2*)p = make_float2(acc[mi][nj][0], acc[mi][nj][1]);
            *(float2*)(p + (size_t)8 * ldc) = make_float2(acc[mi][nj][2], acc[mi][nj][3]);
            ss0 += acc[mi][nj][0] * acc[mi][nj][0] + acc[mi][nj][1] * acc[mi][nj][1];
            ss8 += acc[mi][nj][2] * acc[mi][nj][2] + acc[mi][nj][3] * acc[mi][nj][3];
        }
        ss0 += __shfl_xor_sync(0xffffffffu, ss0, 1);
        ss0 += __shfl_xor_sync(0xffffffffu, ss0, 2);
        ss8 += __shfl_xor_sync(0xffffffffu, ss8, 1);
        ss8 += __shfl_xor_sync(0xffffffffu, ss8, 2);
        if ((l & 3) == 0) {
            int nt = n0 >> 7;
            g_ss[(size_t)(m0 + r0) * 16 + nt]     = ss0;
            g_ss[(size_t)(m0 + r0 + 8) * 16 + nt] = ss8;
        }
    }
}

// ---------------- fused weight splits ----------------
__global__ void __launch_bounds__(256) wsplit(const float* __restrict__ Wq,
                                              const float* __restrict__ Wk,
                                              const float* __restrict__ Wv,
                                              const float* __restrict__ Wo)
{
    int z = blockIdx.y;
    const float* src; unsigned char* dst; int K;
    if (z == 0)      { src = Wq; dst = g_wqs; K = Hh; }
    else if (z == 1) { src = Wk; dst = g_wks; K = Hh; }
    else if (z == 2) { src = Wv; dst = g_wvs; K = Hh; }
    else             { src = Wo; dst = g_wos; K = Mm; }
    int cpr = K >> 3, nkb = K >> 5;
    int g = blockIdx.x * 256 + threadIdx.x;
    int row = g / cpr, pos = g - row * cpr;
    const float4* s = (const float4*)(src + (size_t)row * K + (size_t)pos * 8);
    float4 a0 = s[0], a1 = s[1];
    uint4 h, lo; pack8(a0, a1, h, lo);
    size_t base = ((size_t)row * nkb + (pos >> 2)) * 128 + (size_t)(pos & 3) * 16;
    *(uint4*)(dst + base)      = h;
    *(uint4*)(dst + base + 64) = lo;
}

// ---------------- per-chunk aggregates (k/v split) ----------------
__global__ void __launch_bounds__(256) agg_kernel()
{
    int i = blockIdx.x, z = blockIdx.y;
    const float* src = z ? g_v : g_k;
    __shared__ float swi[256];
    __shared__ float red[256];
    __shared__ float meanb[128];
    int tid = threadIdx.x;
    {
        int b = tid >> 6, c = tid & 63;
        size_t t = (size_t)b * Ss + (size_t)i * CH + c;
        const float4* r4 = (const float4*)(src + t * Mm);
        float n = 0.f;
#pragma unroll 8
        for (int d = 0; d < 32; d++) {
            float4 a = r4[d]; n += a.x * a.x + a.y * a.y + a.z * a.z + a.w * a.w;
        }
        float wv = g_w[t];
        swi[tid] = wv * (1.f / fmaxf(sqrtf(n), 1e-12f));
        red[tid] = wv;
    }
    __syncthreads();
    for (int o = 128; o; o >>= 1) { if (tid < o) red[tid] += red[tid + o]; __syncthreads(); }
    float sumw = red[0];
    float wsum = fmaxf(sumw, 1e-8f);
    __syncthreads();

    int d = tid & 127, h = tid >> 7;
    float acc = 0.f;
#pragma unroll 4
    for (int jj = 0; jj < 128; jj++) {
        int j = h * 128 + jj;
        size_t tj = (size_t)(j >> 6) * Ss + (size_t)i * CH + (j & 63);
        acc += swi[j] * src[tj * Mm + d];
    }
    red[tid] = acc;
    __syncthreads();
    if (h == 0) {
        float mean = (red[d] + red[d + 128]) / wsum;
        meanb[d] = mean;
        red[d] = mean * mean;
    }
    __syncthreads();
    for (int o = 64; o; o >>= 1) { if (tid < o) red[tid] += red[tid + o]; __syncthreads(); }
    float nrm = fmaxf(sqrtf(red[0]), 1e-12f);
    if (h == 0) {
        float outv = meanb[d] / nrm;
        if (z) g_Vagg[i * Mm + d] = outv;
        else   g_Kagg[i * Mm + d] = outv;
    }
    if (z == 0 && tid == 0) g_ws[i] = sumw * (1.f / 256.f);
}

// ---------------- attention read + fused r-split + fused mean_ws ----------------
#define ATTN_SMEM ((8192 + 8192 + 4096 + 8192) * 4)   // 112KB
__global__ void __launch_bounds__(256) attn_kernel(const float* __restrict__ log_beta,
                                                   float* __restrict__ out, int out_size)
{
    extern __shared__ float sm[];
    float* kt  = sm;
    float* vsm = kt + 8192;
    float* psm = vsm + 8192;
    float* qsm = psm + 4096;
    __shared__ float str[64];
    __shared__ float ssum;

    int i = blockIdx.x;
    int bb = blockIdx.y;
    int tid = threadIdx.x;
    float beta = expf(log_beta[0]);
    size_t tbase = (size_t)bb * Ss + (size_t)i * CH;

    for (int idx = tid; idx < 8192; idx += 256) {
        int d = idx >> 6, slot = idx & 63;
        kt[idx] = g_Kagg[slot * 128 + d];
    }
    for (int idx = tid; idx < 8192; idx += 256) vsm[idx] = g_Vagg[idx];
    for (int idx = tid; idx < 8192; idx += 256)
        qsm[idx] = g_q[(tbase + (size_t)(idx >> 7)) * Mm + (idx & 127)];
    if (tid < 64) {
        float dc = powf(0.999f, 64.f);
        float s = 0.f;
        if (tid < i) s = g_ws[tid] * powf(dc, (float)(i - 1 - tid));
        str[tid] = s;
    }
    __syncthreads();
    if (tid == 0) {
        float s = 0.f;
        for (int j = 0; j < 64; j++) s += str[j];
        ssum = s;
        if (i == 0 && bb == 0 && out_size > NTOK * Hh) {
            float m = 0.f;
            for (int j = 0; j < NC; j++) m += g_ws[j];
            out[(size_t)NTOK * Hh] = m / (float)NC;
        }
    }
    __syncthreads();

    bool valid = (ssum >= 1e-8f);
    int w = tid >> 5, lane = tid & 31;
    float m0ok = (str[lane] > 1e-8f)      ? 0.f : -1e9f;
    float m1ok = (str[lane + 32] > 1e-8f) ? 0.f : -1e9f;

    float s0[8], s1[8];
#pragma unroll
    for (int c8 = 0; c8 < 8; c8++) { s0[c8] = 0.f; s1[c8] = 0.f; }
    for (int d4 = 0; d4 < 32; d4++) {
        float kv0[4], kv1[4];
#pragma unroll
        for (int ii = 0; ii < 4; ii++) {
            kv0[ii] = kt[(d4 * 4 + ii) * 64 + lane];
            kv1[ii] = kt[(d4 * 4 + ii) * 64 + 32 + lane];
        }
#pragma unroll
        for (int c8 = 0; c8 < 8; c8++) {
            float4 q = *(const float4*)(qsm + (w * 8 + c8) * 128 + d4 * 4);
            s0[c8] += q.x * kv0[0] + q.y * kv0[1] + q.z * kv0[2] + q.w * kv0[3];
            s1[c8] += q.x * kv1[0] + q.y * kv1[1] + q.z * kv1[2] + q.w * kv1[3];
        }
    }
#pragma unroll
    for (int c8 = 0; c8 < 8; c8++) {
        float sv0 = s0[c8] * beta + m0ok;
        float sv1 = s1[c8] * beta + m1ok;
        float mx = fmaxf(sv0, sv1);
#pragma unroll
        for (int o = 16; o; o >>= 1) mx = fmaxf(mx, __shfl_xor_sync(0xffffffffu, mx, o));
        float p0 = expf(sv0 - mx);
        float p1 = expf(sv1 - mx);
        float sum = p0 + p1;
#pragma unroll
        for (int o = 16; o; o >>= 1) sum += __shfl_xor_sync(0xffffffffu, sum, o);
        float invs = 1.f / sum;
        psm[w * 512 + c8 * 64 + lane]      = p0 * invs;
        psm[w * 512 + c8 * 64 + 32 + lane] = p1 * invs;
    }
    __syncthreads();

    float a[8][4];
#pragma unroll
    for (int c8 = 0; c8 < 8; c8++)
#pragma unroll
        for (int cc = 0; cc < 4; cc++) a[c8][cc] = 0.f;
    for (int j = 0; j < 64; j++) {
        float v0 = vsm[j * 128 + lane];
        float v1 = vsm[j * 128 + 32 + lane];
        float v2 = vsm[j * 128 + 64 + lane];
        float v3 = vsm[j * 128 + 96 + lane];
#pragma unroll
        for (int c8 = 0; c8 < 8; c8++) {
            float pj = psm[w * 512 + c8 * 64 + j];
            a[c8][0] += pj * v0; a[c8][1] += pj * v1;
            a[c8][2] += pj * v2; a[c8][3] += pj * v3;
        }
    }
    float* rsm = kt;
#pragma unroll
    for (int c8 = 0; c8 < 8; c8++) {
        int lt = w * 8 + c8;
        rsm[lt * 128 + lane]      = valid ? a[c8][0] : 0.f;
        rsm[lt * 128 + lane + 32] = valid ? a[c8][1] : 0.f;
        rsm[lt * 128 + lane + 64] = valid ? a[c8][2] : 0.f;
        rsm[lt * 128 + lane + 96] = valid ? a[c8][3] : 0.f;
    }
    __syncthreads();

#pragma unroll
    for (int u = 0; u < 4; u++) {
        int c = tid + (u << 8);
        int lt = c >> 4, pos = c & 15;
        float4 a0 = *(float4*)(rsm + lt * 128 + pos * 8);
        float4 a1 = *(float4*)(rsm + lt * 128 + pos * 8 + 4);
        uint4 h, lo; pack8(a0, a1, h, lo);
        size_t grow = tbase + lt;
        size_t base = (grow * 4 + (size_t)(pos >> 2)) * 128 + (size_t)(pos & 3) * 16;
        *(uint4*)(g_rs + base)      = h;
        *(uint4*)(g_rs + base + 64) = lo;
    }
}

// ---------------- norm clamp from precomputed partial sums ----------------
__global__ void __launch_bounds__(256) norm2_kernel(float* __restrict__ out)
{
    int tok = blockIdx.x * 8 + (threadIdx.x >> 5);
    int lane = threadIdx.x & 31;
    float s = (lane < 16) ? g_ss[(size_t)tok * 16 + lane] : 0.f;
#pragma unroll
    for (int o = 16; o; o >>= 1) s += __shfl_xor_sync(0xffffffffu, s, o);
    float nrm = fmaxf(sqrtf(s), 1e-6f);
    float sc = fminf(10.f / nrm, 1.f);
    if (sc < 1.f) {
        float4* row = (float4*)(out + (size_t)tok * Hh);
#pragma unroll 4
        for (int j = lane; j < 512; j += 32) {
            float4 v = row[j];
            v.x *= sc; v.y *= sc; v.z *= sc; v.w *= sc;
            row[j] = v;
        }
    }
}

// ---------------- launch ----------------
extern "C" void kernel_launch(void* const* d_in, const int* in_sizes, int n_in,
                              void* d_out, int out_size)
{
    const float* x  = (const float*)d_in[0];
    const float* Wq = (const float*)d_in[1];
    const float* Wk = (const float*)d_in[2];
    const float* Wv = (const float*)d_in[3];
    const float* Wo = (const float*)d_in[4];
    const float* Wg = (const float*)d_in[5];
    const float* gb = (const float*)d_in[6];
    const float* lb = (const float*)d_in[7];
    float* out = (float*)d_out;

    cudaFuncSetAttribute(attn_kernel, cudaFuncAttributeMaxDynamicSharedMemorySize, ATTN_SMEM);
    cudaFuncSetAttribute(mega_proj6, cudaFuncAttributeMaxDynamicSharedMemorySize, MEGA6_SMEM);
    cudaFuncSetAttribute(out_mma,  cudaFuncAttributeMaxDynamicSharedMemorySize, GEMM_SMEM);

    // 1. all weight splits in one launch
    wsplit<<<dim3(128, 4), 256>>>(Wq, Wk, Wv, Wo);
    // 2. fused split + gate + q/k/v projections (out_mma-shaped, 2 CTA/SM)
    mega_proj6<<<dim3(3, NTOK / 128), 256, MEGA6_SMEM>>>(x, Wg, gb);
    // 3. per-chunk write aggregates (k/v parallel)
    agg_kernel<<<dim3(NC, 2), 256>>>();
    // 4. attention reads (+ fused r-split + mean_ws)
    attn_kernel<<<dim3(NC, Bb), 256, ATTN_SMEM>>>(lb, out, out_size);
    // 5. output projection (+ per-row ss partials)
    out_mma<<<dim3(NTOK / 128, Hh / 128), 256, GEMM_SMEM>>>(out);
    // 6. norm clamp from partials
    norm2_kernel<<<NTOK / 8, 256>>>(out);
}

// round 17
// speedup vs baseline: 1.3006x; 1.3006x over previous
#include <cuda_runtime.h>
#include <cuda_bf16.h>
#include <math.h>
#include <stdint.h>

#define Bb 4
#define Ss 4096
#define Hh 2048
#define Mm 128
#define CH 64
#define NC 64
#define NSLOTS 64
#define NTOK (Bb*Ss)   // 16384

// ---------------- scratch ----------------
__device__ float g_q[NTOK*Mm];
__device__ float g_k[NTOK*Mm];
__device__ float g_v[NTOK*Mm];
__device__ float g_w[NTOK];
__device__ float g_ss[NTOK*16];
__device__ float g_Kagg[NSLOTS*Mm];
__device__ float g_Vagg[NSLOTS*Mm];
__device__ float g_ws[NSLOTS];
__device__ __align__(128) unsigned char g_rs [(size_t)NTOK * Mm * 4];
__device__ __align__(128) unsigned char g_wqs[(size_t)Mm * Hh * 4];
__device__ __align__(128) unsigned char g_wks[(size_t)Mm * Hh * 4];
__device__ __align__(128) unsigned char g_wvs[(size_t)Mm * Hh * 4];
__device__ __align__(128) unsigned char g_wos[(size_t)Hh * Mm * 4];

// ================= helpers =================
__device__ __forceinline__ uint32_t smem_u32(const void* p){
    uint32_t a;
    asm("{ .reg .u64 t; cvta.to.shared.u64 t, %1; cvt.u32.u64 %0, t; }" : "=r"(a) : "l"(p));
    return a;
}
__device__ __forceinline__ uint32_t bf2(float x, float y){
    uint32_t r; asm("cvt.rn.bf16x2.f32 %0, %1, %2;" : "=r"(r) : "f"(y), "f"(x)); return r;
}
__device__ __forceinline__ uint32_t swz(uint32_t x){ return x ^ (((x) >> 3) & 0x70); }

__device__ __forceinline__ void pack4(float4 a, uint2& h, uint2& lo){
    h.x = bf2(a.x, a.y); h.y = bf2(a.z, a.w);
    float l0 = a.x - __uint_as_float(h.x << 16);
    float l1 = a.y - __uint_as_float(h.x & 0xffff0000u);
    float l2 = a.z - __uint_as_float(h.y << 16);
    float l3 = a.w - __uint_as_float(h.y & 0xffff0000u);
    lo.x = bf2(l0, l1); lo.y = bf2(l2, l3);
}
__device__ __forceinline__ void pack8(float4 a0, float4 a1, uint4& h, uint4& lo){
    uint2 h0, l0, h1, l1;
    pack4(a0, h0, l0); pack4(a1, h1, l1);
    h.x = h0.x; h.y = h0.y; h.z = h1.x; h.w = h1.y;
    lo.x = l0.x; lo.y = l0.y; lo.z = l1.x; lo.w = l1.y;
}

#define LDSM4(r, addr) \
    asm volatile("ldmatrix.sync.aligned.m8n8.x4.shared.b16 {%0,%1,%2,%3}, [%4];" \
        : "=r"((r)[0]), "=r"((r)[1]), "=r"((r)[2]), "=r"((r)[3]) : "r"(addr))

#define MMA16816(d, a, b0, b1) \
    asm volatile("mma.sync.aligned.m16n8k16.row.col.f32.bf16.bf16.f32 " \
        "{%0,%1,%2,%3}, {%4,%5,%6,%7}, {%8,%9}, {%0,%1,%2,%3};" \
        : "+f"((d)[0]), "+f"((d)[1]), "+f"((d)[2]), "+f"((d)[3]) \
        : "r"((a)[0]), "r"((a)[1]), "r"((a)[2]), "r"((a)[3]), "r"(b0), "r"(b1))

#define CP16(dst, src) \
    asm volatile("cp.async.cg.shared.global [%0], [%1], 16;" :: "r"(dst), "l"(src) : "memory")
#define CP_COMMIT() asm volatile("cp.async.commit_group;" ::: "memory")
#define CP_WAIT1()  asm volatile("cp.async.wait_group 1;" ::: "memory")

// ======================================================================
// mega_proj v4r: R15 layout, MMAs reordered term-major (hh*12, hl*12, lh*12)
// to break per-accumulator RAW chains. Bit-identical accumulation order.
// ======================================================================
#define PNSTG 3
#define BSP_OFF(s, z) ((s) * 49152 + (z) * 16384)
#define ABF_OFF(p)    (147456 + (p) * 8192)
#define WG_OFF        163840
#define MEGA_SMEM     172032

__global__ void __launch_bounds__(512, 1) mega_proj(const float* __restrict__ x,
                                                    const float* __restrict__ Wg,
                                                    const float* __restrict__ gb)
{
    extern __shared__ __align__(1024) char smem[];
    __shared__ float gred[64][8];
    int tid = threadIdx.x;
    int w = tid >> 5, l = tid & 31;
    int m0 = blockIdx.x * 64;
    uint32_t smb = smem_u32(smem);
    const int NB = Hh / 32;   // 64

    unsigned long long gWq = (unsigned long long)__cvta_generic_to_global(g_wqs);
    unsigned long long gWk = (unsigned long long)__cvta_generic_to_global(g_wks);
    unsigned long long gWv = (unsigned long long)__cvta_generic_to_global(g_wvs);

    {
        const float4* wg4 = (const float4*)Wg;
        *(float4*)(smem + WG_OFF + tid * 16) = wg4[tid];
    }

    int row = tid >> 3;     // 0..63
    int chk = tid & 7;      // 0..7

    auto issueB = [&](int kb) {
        int s = kb % PNSTG;
        unsigned long long gws[3] = {gWq, gWk, gWv};
#pragma unroll
        for (int z = 0; z < 3; z++) {
            uint32_t stB = smb + BSP_OFF(s, z);
#pragma unroll
            for (int u = 0; u < 2; u++) {
                int c = tid + (u << 9);
                int r = c >> 3;
                uint32_t seg = (uint32_t)(c & 7) << 4;
                unsigned long long src = gws[z] + ((unsigned long long)r * NB + kb) * 128ull + seg;
                CP16(stB + swz(((uint32_t)r << 7) + seg), src);
            }
        }
    };

    auto ldgA = [&](int kb, float4& a0) {
        a0 = __ldg((const float4*)(x + (size_t)(m0 + row) * Hh + (size_t)kb * 32 + chk * 4));
    };

    float gp0 = 0.f;

    auto split_phase = [&](int kb, float4 a0) {
        char* abf = smem + ABF_OFF(kb & 1);
        const float* wgs = (const float*)(smem + WG_OFF) + kb * 32 + chk * 4;
        gp0 += a0.x * wgs[0] + a0.y * wgs[1] + a0.z * wgs[2] + a0.w * wgs[3];
        uint2 h0, lo0;
        pack4(a0, h0, lo0);
        uint32_t b0 = (uint32_t)row * 128 + (uint32_t)chk * 8;
        *(uint2*)(abf + swz(b0))      = h0;
        *(uint2*)(abf + swz(b0 + 64)) = lo0;
    };

    float acc[3][2][2][4];
#pragma unroll
    for (int z = 0; z < 3; z++)
#pragma unroll
        for (int mi = 0; mi < 2; mi++)
#pragma unroll
            for (int nj = 0; nj < 2; nj++)
#pragma unroll
                for (int cc = 0; cc < 4; cc++) acc[z][mi][nj][cc] = 0.f;

    int mw = w >> 3;          // 0..1
    int nw = w & 7;           // 0..7
    int lr = l & 15, lh = l >> 4;

    issueB(0); CP_COMMIT();
    issueB(1); CP_COMMIT();
    float4 a0;
    ldgA(0, a0);
    __syncthreads();
    split_phase(0, a0);
    ldgA(1, a0);

    for (int kb = 0; kb < NB; kb++) {
        CP_WAIT1();
        __syncthreads();
        if (kb + 2 < NB) { issueB(kb + 2); }
        CP_COMMIT();
        if (kb + 1 < NB) {
            split_phase(kb + 1, a0);
            int kn = (kb + 2 < NB) ? (kb + 2) : (NB - 1);
            ldgA(kn, a0);
        }

        int s = kb % PNSTG;
        uint32_t sAu = smb + ABF_OFF(kb & 1);
#pragma unroll
        for (int ks = 0; ks < 2; ks++) {
            uint32_t kbyte = (uint32_t)(ks << 5) + (lh << 4);
            uint32_t Ah[2][4], Al[2][4], Bh3[3][4], Bl3[3][4];
#pragma unroll
            for (int t = 0; t < 2; t++) {
                uint32_t ro = (uint32_t)((mw * 32 + (t << 4) + lr) << 7) + kbyte;
                LDSM4(Ah[t], sAu + swz(ro));
                LDSM4(Al[t], sAu + swz(ro + 64));
            }
#pragma unroll
            for (int z = 0; z < 3; z++) {
                uint32_t sBu = smb + BSP_OFF(s, z);
                uint32_t ro = (uint32_t)((nw * 16 + lr) << 7) + kbyte;
                LDSM4(Bh3[z], sBu + swz(ro));
                LDSM4(Bl3[z], sBu + swz(ro + 64));
            }
            // term-major: hh then hl then lh — 12 independent MMAs per term
#pragma unroll
            for (int z = 0; z < 3; z++)
#pragma unroll
                for (int mi = 0; mi < 2; mi++)
#pragma unroll
                    for (int j = 0; j < 2; j++)
                        MMA16816(acc[z][mi][j], Ah[mi], Bh3[z][j], Bh3[z][j + 2]);
#pragma unroll
            for (int z = 0; z < 3; z++)
#pragma unroll
                for (int mi = 0; mi < 2; mi++)
#pragma unroll
                    for (int j = 0; j < 2; j++)
                        MMA16816(acc[z][mi][j], Ah[mi], Bl3[z][j], Bl3[z][j + 2]);
#pragma unroll
            for (int z = 0; z < 3; z++)
#pragma unroll
                for (int mi = 0; mi < 2; mi++)
#pragma unroll
                    for (int j = 0; j < 2; j++)
                        MMA16816(acc[z][mi][j], Al[mi], Bh3[z][j], Bh3[z][j + 2]);
        }
    }

    gred[row][chk] = gp0;
    __syncthreads();
    if (tid < 64) {
        float s = 0.f;
#pragma unroll
        for (int j = 0; j < 8; j++) s += gred[tid][j];
        g_w[m0 + tid] = 1.f / (1.f + expf(-(s + gb[0])));
    }

    float* Cs[3] = {g_q, g_k, g_v};
#pragma unroll
    for (int z = 0; z < 3; z++) {
#pragma unroll
        for (int mi = 0; mi < 2; mi++) {
            int r0 = mw * 32 + (mi << 4) + (l >> 2);
#pragma unroll
            for (int j = 0; j < 2; j++) {
                float* p = Cs[z] + (size_t)(m0 + r0) * Mm + nw * 16 + (j << 3) + ((l & 3) << 1);
                *(float2*)p = make_float2(acc[z][mi][j][0], acc[z][mi][j][1]);
                *(float2*)(p + (size_t)8 * Mm) = make_float2(acc[z][mi][j][2], acc[z][mi][j][3]);
            }
        }
    }
}

// ======================================================================
// out gemm (+ ss partials), MMAs reordered term-major
// ======================================================================
#define NSTG 2
#define STAGE_B 32768
#define GEMM_SMEM (NSTG * STAGE_B)   // 64 KB

__global__ void __launch_bounds__(256, 2) out_mma(float* __restrict__ out)
{
    extern __shared__ __align__(1024) char smem[];
    int n0 = blockIdx.y * 128;
    int m0 = blockIdx.x * 128;
    const unsigned char* As = g_rs;
    const unsigned char* Bs = g_wos + (size_t)n0 * 4 * 128;
    float* C = out + n0;
    const int NB = Mm / 32, ldc = Hh;

    int tid = threadIdx.x;
    int w = tid >> 5, l = tid & 31;
    uint32_t smb = smem_u32(smem);
    unsigned long long gA = (unsigned long long)__cvta_generic_to_global(As);
    unsigned long long gB = (unsigned long long)__cvta_generic_to_global(Bs);

    auto issue = [&](int kb) {
        uint32_t st = smb + (uint32_t)(kb & (NSTG - 1)) * STAGE_B;
#pragma unroll
        for (int u = 0; u < 4; u++) {
            int c = tid + (u << 8);
            int row = c >> 3;
            uint32_t seg = (uint32_t)(c & 7) << 4;
            unsigned long long srcA = gA + ((unsigned long long)(m0 + row) * NB + kb) * 128ull + seg;
            unsigned long long srcB = gB + ((unsigned long long)row * NB + kb) * 128ull + seg;
            uint32_t d = swz(((uint32_t)row << 7) + seg);
            CP16(st + d, srcA);
            CP16(st + 16384 + d, srcB);
        }
    };

    float acc[2][8][4];
#pragma unroll
    for (int mi = 0; mi < 2; mi++)
#pragma unroll
        for (int nj = 0; nj < 8; nj++)
#pragma unroll
            for (int cc = 0; cc < 4; cc++) acc[mi][nj][cc] = 0.f;

    int wm = (w >> 1) << 5;
    int wn = (w & 1) << 6;
    int lr = l & 15, lh = l >> 4;

    issue(0); CP_COMMIT();
    issue(1); CP_COMMIT();

    for (int kb = 0; kb < NB; kb++) {
        CP_WAIT1();
        __syncthreads();
        uint32_t sAu = smb + (uint32_t)(kb & (NSTG - 1)) * STAGE_B;
        uint32_t sBu = sAu + 16384;
#pragma unroll
        for (int ks = 0; ks < 2; ks++) {
            uint32_t kbyte = (uint32_t)(ks << 5) + (lh << 4);
            uint32_t Ah[2][4], Al[2][4], Bh[4][4], Bl[4][4];
#pragma unroll
            for (int t = 0; t < 2; t++) {
                uint32_t ro = (uint32_t)((wm + (t << 4) + lr) << 7) + kbyte;
                LDSM4(Ah[t], sAu + swz(ro));
                LDSM4(Al[t], sAu + swz(ro + 64));
            }
#pragma unroll
            for (int g = 0; g < 4; g++) {
                uint32_t ro = (uint32_t)((wn + (g << 4) + lr) << 7) + kbyte;
                LDSM4(Bh[g], sBu + swz(ro));
                LDSM4(Bl[g], sBu + swz(ro + 64));
            }
            // term-major: hh*16, hl*16, lh*16
#pragma unroll
            for (int mi = 0; mi < 2; mi++)
#pragma unroll
                for (int nj = 0; nj < 8; nj++) {
                    int g = nj >> 1, p = nj & 1;
                    MMA16816(acc[mi][nj], Ah[mi], Bh[g][p], Bh[g][p + 2]);
                }
#pragma unroll
            for (int mi = 0; mi < 2; mi++)
#pragma unroll
                for (int nj = 0; nj < 8; nj++) {
                    int g = nj >> 1, p = nj & 1;
                    MMA16816(acc[mi][nj], Ah[mi], Bl[g][p], Bl[g][p + 2]);
                }
#pragma unroll
            for (int mi = 0; mi < 2; mi++)
#pragma unroll
                for (int nj = 0; nj < 8; nj++) {
                    int g = nj >> 1, p = nj & 1;
                    MMA16816(acc[mi][nj], Al[mi], Bh[g][p], Bh[g][p + 2]);
                }
        }
        __syncthreads();
        if (kb + NSTG < NB) issue(kb + NSTG);
        CP_COMMIT();
    }

#pragma unroll
    for (int mi = 0; mi < 2; mi++) {
        int r0 = wm + (mi << 4) + (l >> 2);
        float ss0 = 0.f, ss8 = 0.f;
#pragma unroll
        for (int nj = 0; nj < 8; nj++) {
            float* p = C + (size_t)(m0 + r0) * ldc + wn + (nj << 3) + ((l & 3) << 1);
            *(float2*)p = make_float2(acc[mi][nj][0], acc[mi][nj][1]);
            *(float2*)(p + (size_t)8 * ldc) = make_float2(acc[mi][nj][2], acc[mi][nj][3]);
            ss0 += acc[mi][nj][0] * acc[mi][nj][0] + acc[mi][nj][1] * acc[mi][nj][1];
            ss8 += acc[mi][nj][2] * acc[mi][nj][2] + acc[mi][nj][3] * acc[mi][nj][3];
        }
        ss0 += __shfl_xor_sync(0xffffffffu, ss0, 1);
        ss0 += __shfl_xor_sync(0xffffffffu, ss0, 2);
        ss8 += __shfl_xor_sync(0xffffffffu, ss8, 1);
        ss8 += __shfl_xor_sync(0xffffffffu, ss8, 2);
        if ((l & 3) == 0) {
            int nt = n0 >> 7;
            g_ss[(size_t)(m0 + r0) * 16 + nt]     = ss0;
            g_ss[(size_t)(m0 + r0 + 8) * 16 + nt] = ss8;
        }
    }
}

// ---------------- fused weight splits ----------------
__global__ void __launch_bounds__(256) wsplit(const float* __restrict__ Wq,
                                              const float* __restrict__ Wk,
                                              const float* __restrict__ Wv,
                                              const float* __restrict__ Wo)
{
    int z = blockIdx.y;
    const float* src; unsigned char* dst; int K;
    if (z == 0)      { src = Wq; dst = g_wqs; K = Hh; }
    else if (z == 1) { src = Wk; dst = g_wks; K = Hh; }
    else if (z == 2) { src = Wv; dst = g_wvs; K = Hh; }
    else             { src = Wo; dst = g_wos; K = Mm; }
    int cpr = K >> 3, nkb = K >> 5;
    int g = blockIdx.x * 256 + threadIdx.x;
    int row = g / cpr, pos = g - row * cpr;
    const float4* s = (const float4*)(src + (size_t)row * K + (size_t)pos * 8);
    float4 a0 = s[0], a1 = s[1];
    uint4 h, lo; pack8(a0, a1, h, lo);
    size_t base = ((size_t)row * nkb + (pos >> 2)) * 128 + (size_t)(pos & 3) * 16;
    *(uint4*)(dst + base)      = h;
    *(uint4*)(dst + base + 64) = lo;
}

// ---------------- per-chunk aggregates (k/v split) ----------------
__global__ void __launch_bounds__(256) agg_kernel()
{
    int i = blockIdx.x, z = blockIdx.y;
    const float* src = z ? g_v : g_k;
    __shared__ float swi[256];
    __shared__ float red[256];
    __shared__ float meanb[128];
    int tid = threadIdx.x;
    {
        int b = tid >> 6, c = tid & 63;
        size_t t = (size_t)b * Ss + (size_t)i * CH + c;
        const float4* r4 = (const float4*)(src + t * Mm);
        float n = 0.f;
#pragma unroll 8
        for (int d = 0; d < 32; d++) {
            float4 a = r4[d]; n += a.x * a.x + a.y * a.y + a.z * a.z + a.w * a.w;
        }
        float wv = g_w[t];
        swi[tid] = wv * (1.f / fmaxf(sqrtf(n), 1e-12f));
        red[tid] = wv;
    }
    __syncthreads();
    for (int o = 128; o; o >>= 1) { if (tid < o) red[tid] += red[tid + o]; __syncthreads(); }
    float sumw = red[0];
    float wsum = fmaxf(sumw, 1e-8f);
    __syncthreads();

    int d = tid & 127, h = tid >> 7;
    float acc = 0.f;
#pragma unroll 4
    for (int jj = 0; jj < 128; jj++) {
        int j = h * 128 + jj;
        size_t tj = (size_t)(j >> 6) * Ss + (size_t)i * CH + (j & 63);
        acc += swi[j] * src[tj * Mm + d];
    }
    red[tid] = acc;
    __syncthreads();
    if (h == 0) {
        float mean = (red[d] + red[d + 128]) / wsum;
        meanb[d] = mean;
        red[d] = mean * mean;
    }
    __syncthreads();
    for (int o = 64; o; o >>= 1) { if (tid < o) red[tid] += red[tid + o]; __syncthreads(); }
    float nrm = fmaxf(sqrtf(red[0]), 1e-12f);
    if (h == 0) {
        float outv = meanb[d] / nrm;
        if (z) g_Vagg[i * Mm + d] = outv;
        else   g_Kagg[i * Mm + d] = outv;
    }
    if (z == 0 && tid == 0) g_ws[i] = sumw * (1.f / 256.f);
}

// ---------------- attention read + fused r-split + fused mean_ws ----------------
#define ATTN_SMEM ((8192 + 8192 + 4096 + 8192) * 4)   // 112KB
__global__ void __launch_bounds__(256) attn_kernel(const float* __restrict__ log_beta,
                                                   float* __restrict__ out, int out_size)
{
    extern __shared__ float sm[];
    float* kt  = sm;
    float* vsm = kt + 8192;
    float* psm = vsm + 8192;
    float* qsm = psm + 4096;
    __shared__ float str[64];
    __shared__ float ssum;

    int i = blockIdx.x;
    int bb = blockIdx.y;
    int tid = threadIdx.x;
    float beta = expf(log_beta[0]);
    size_t tbase = (size_t)bb * Ss + (size_t)i * CH;

    for (int idx = tid; idx < 8192; idx += 256) {
        int d = idx >> 6, slot = idx & 63;
        kt[idx] = g_Kagg[slot * 128 + d];
    }
    for (int idx = tid; idx < 8192; idx += 256) vsm[idx] = g_Vagg[idx];
    for (int idx = tid; idx < 8192; idx += 256)
        qsm[idx] = g_q[(tbase + (size_t)(idx >> 7)) * Mm + (idx & 127)];
    if (tid < 64) {
        float dc = powf(0.999f, 64.f);
        float s = 0.f;
        if (tid < i) s = g_ws[tid] * powf(dc, (float)(i - 1 - tid));
        str[tid] = s;
    }
    __syncthreads();
    if (tid == 0) {
        float s = 0.f;
        for (int j = 0; j < 64; j++) s += str[j];
        ssum = s;
        if (i == 0 && bb == 0 && out_size > NTOK * Hh) {
            float m = 0.f;
            for (int j = 0; j < NC; j++) m += g_ws[j];
            out[(size_t)NTOK * Hh] = m / (float)NC;
        }
    }
    __syncthreads();

    bool valid = (ssum >= 1e-8f);
    int w = tid >> 5, lane = tid & 31;
    float m0ok = (str[lane] > 1e-8f)      ? 0.f : -1e9f;
    float m1ok = (str[lane + 32] > 1e-8f) ? 0.f : -1e9f;

    float s0[8], s1[8];
#pragma unroll
    for (int c8 = 0; c8 < 8; c8++) { s0[c8] = 0.f; s1[c8] = 0.f; }
    for (int d4 = 0; d4 < 32; d4++) {
        float kv0[4], kv1[4];
#pragma unroll
        for (int ii = 0; ii < 4; ii++) {
            kv0[ii] = kt[(d4 * 4 + ii) * 64 + lane];
            kv1[ii] = kt[(d4 * 4 + ii) * 64 + 32 + lane];
        }
#pragma unroll
        for (int c8 = 0; c8 < 8; c8++) {
            float4 q = *(const float4*)(qsm + (w * 8 + c8) * 128 + d4 * 4);
            s0[c8] += q.x * kv0[0] + q.y * kv0[1] + q.z * kv0[2] + q.w * kv0[3];
            s1[c8] += q.x * kv1[0] + q.y * kv1[1] + q.z * kv1[2] + q.w * kv1[3];
        }
    }
#pragma unroll
    for (int c8 = 0; c8 < 8; c8++) {
        float sv0 = s0[c8] * beta + m0ok;
        float sv1 = s1[c8] * beta + m1ok;
        float mx = fmaxf(sv0, sv1);
#pragma unroll
        for (int o = 16; o; o >>= 1) mx = fmaxf(mx, __shfl_xor_sync(0xffffffffu, mx, o));
        float p0 = expf(sv0 - mx);
        float p1 = expf(sv1 - mx);
        float sum = p0 + p1;
#pragma unroll
        for (int o = 16; o; o >>= 1) sum += __shfl_xor_sync(0xffffffffu, sum, o);
        float invs = 1.f / sum;
        psm[w * 512 + c8 * 64 + lane]      = p0 * invs;
        psm[w * 512 + c8 * 64 + 32 + lane] = p1 * invs;
    }
    __syncthreads();

    float a[8][4];
#pragma unroll
    for (int c8 = 0; c8 < 8; c8++)
#pragma unroll
        for (int cc = 0; cc < 4; cc++) a[c8][cc] = 0.f;
    for (int j = 0; j < 64; j++) {
        float v0 = vsm[j * 128 + lane];
        float v1 = vsm[j * 128 + 32 + lane];
        float v2 = vsm[j * 128 + 64 + lane];
        float v3 = vsm[j * 128 + 96 + lane];
#pragma unroll
        for (int c8 = 0; c8 < 8; c8++) {
            float pj = psm[w * 512 + c8 * 64 + j];
            a[c8][0] += pj * v0; a[c8][1] += pj * v1;
            a[c8][2] += pj * v2; a[c8][3] += pj * v3;
        }
    }
    float* rsm = kt;
#pragma unroll
    for (int c8 = 0; c8 < 8; c8++) {
        int lt = w * 8 + c8;
        rsm[lt * 128 + lane]      = valid ? a[c8][0] : 0.f;
        rsm[lt * 128 + lane + 32] = valid ? a[c8][1] : 0.f;
        rsm[lt * 128 + lane + 64] = valid ? a[c8][2] : 0.f;
        rsm[lt * 128 + lane + 96] = valid ? a[c8][3] : 0.f;
    }
    __syncthreads();

#pragma unroll
    for (int u = 0; u < 4; u++) {
        int c = tid + (u << 8);
        int lt = c >> 4, pos = c & 15;
        float4 a0 = *(float4*)(rsm + lt * 128 + pos * 8);
        float4 a1 = *(float4*)(rsm + lt * 128 + pos * 8 + 4);
        uint4 h, lo; pack8(a0, a1, h, lo);
        size_t grow = tbase + lt;
        size_t base = (grow * 4 + (size_t)(pos >> 2)) * 128 + (size_t)(pos & 3) * 16;
        *(uint4*)(g_rs + base)      = h;
        *(uint4*)(g_rs + base + 64) = lo;
    }
}

// ---------------- norm clamp from precomputed partial sums ----------------
__global__ void __launch_bounds__(256) norm2_kernel(float* __restrict__ out)
{
    int tok = blockIdx.x * 8 + (threadIdx.x >> 5);
    int lane = threadIdx.x & 31;
    float s = (lane < 16) ? g_ss[(size_t)tok * 16 + lane] : 0.f;
#pragma unroll
    for (int o = 16; o; o >>= 1) s += __shfl_xor_sync(0xffffffffu, s, o);
    float nrm = fmaxf(sqrtf(s), 1e-6f);
    float sc = fminf(10.f / nrm, 1.f);
    if (sc < 1.f) {
        float4* row = (float4*)(out + (size_t)tok * Hh);
#pragma unroll 4
        for (int j = lane; j < 512; j += 32) {
            float4 v = row[j];
            v.x *= sc; v.y *= sc; v.z *= sc; v.w *= sc;
            row[j] = v;
        }
    }
}

// ---------------- launch ----------------
extern "C" void kernel_launch(void* const* d_in, const int* in_sizes, int n_in,
                              void* d_out, int out_size)
{
    const float* x  = (const float*)d_in[0];
    const float* Wq = (const float*)d_in[1];
    const float* Wk = (const float*)d_in[2];
    const float* Wv = (const float*)d_in[3];
    const float* Wo = (const float*)d_in[4];
    const float* Wg = (const float*)d_in[5];
    const float* gb = (const float*)d_in[6];
    const float* lb = (const float*)d_in[7];
    float* out = (float*)d_out;

    cudaFuncSetAttribute(attn_kernel, cudaFuncAttributeMaxDynamicSharedMemorySize, ATTN_SMEM);
    cudaFuncSetAttribute(mega_proj, cudaFuncAttributeMaxDynamicSharedMemorySize, MEGA_SMEM);
    cudaFuncSetAttribute(out_mma,  cudaFuncAttributeMaxDynamicSharedMemorySize, GEMM_SMEM);

    // 1. all weight splits in one launch
    wsplit<<<dim3(128, 4), 256>>>(Wq, Wk, Wv, Wo);
    // 2. fused split + gate + q/k/v projections (term-major MMA issue)
    mega_proj<<<NTOK / 64, 512, MEGA_SMEM>>>(x, Wg, gb);
    // 3. per-chunk write aggregates (k/v parallel)
    agg_kernel<<<dim3(NC, 2), 256>>>();
    // 4. attention reads (+ fused r-split + mean_ws)
    attn_kernel<<<dim3(NC, Bb), 256, ATTN_SMEM>>>(lb, out, out_size);
    // 5. output projection (+ ss partials, term-major MMA issue)
    out_mma<<<dim3(NTOK / 128, Hh / 128), 256, GEMM_SMEM>>>(out);
    // 6. norm clamp from partials
    norm2_kernel<<<NTOK / 8, 256>>>(out);
}